// round 12
// baseline (speedup 1.0000x reference)
#include <cuda_runtime.h>
#include <cuda_bf16.h>

#define L 45
#define NS 64              // ull slots per e-buffer (46 live incl pad, rest dump)
#define SMAX 512
#define START_IDX 43
#define STOP_IDX 44
#define PF 4               // logit prefetch distance (steps)
#define LOG2E 1.4426950408889634f
#define LN2   0.6931471805599453f
#define FULLM 0xFFFFFFFFu

typedef unsigned long long ull;

__device__ __forceinline__ float ex2f(float x) {
    float r; asm("ex2.approx.ftz.f32 %0, %1;" : "=f"(r) : "f"(x)); return r;
}
__device__ __forceinline__ float lg2f(float x) {
    float r; asm("lg2.approx.ftz.f32 %0, %1;" : "=f"(r) : "f"(x)); return r;
}
__device__ __forceinline__ void fma2(ull& d, ull a, ull b) {
    asm("fma.rn.f32x2 %0, %1, %2, %0;" : "+l"(d) : "l"(a), "l"(b));
}
__device__ __forceinline__ void add2(ull& d, ull a) {
    asm("add.rn.f32x2 %0, %0, %1;" : "+l"(d) : "l"(a));
}
__device__ __forceinline__ ull pack2(float lo, float hi) {
    ull v; asm("mov.b64 %0, {%1, %2};" : "=l"(v) : "f"(lo), "f"(hi)); return v;
}
__device__ __forceinline__ float2 unpack2(ull v) {
    float2 f; asm("mov.b64 {%0, %1}, %2;" : "=f"(f.x), "=f"(f.y) : "l"(v)); return f;
}

// ONE BATCH PER WARP, 4 warps/block (wid%4 -> all four SMSPs). The step body
// is 100% branch-free and divergence-free (no BSSY/BSYNC): all 32 lanes run
// identical code; lanes >= 23 compute zeros into dump slots.
//   lane k owns labels {2k, 2k+1} (lane 22: {44, pad45}); its f32x2
//   accumulator pair IS (s_2k, s_2k+1) -- no cross-lane reduction.
//   e exchanged via per-warp smem, stored duplicated (e,e) per 8B slot so the
//   dot reads broadcast LDS.128. ALL lanes STS.128 unconditionally (pads
//   absorb garbage; rowp[45] = 0 kills pad slot 45 in the dot).
//   Scale increment: every lane redundantly computes cn = lg2(s_lo) + x_lo;
//   next step shfl's lane 0's cn (stale-by-one, off the critical path).
// Recurrence (base-2, scaled-linear): s_i = sum_j expT[i,j]*e[j];
//   e'_i = s_i * 2^(lgt_i*log2e - c);  M2 += c;  alpha_i = (M2+lg2 e_i)*ln2.
__global__ __launch_bounds__(128) void crf_fwd_kernel(
    const float* __restrict__ logits,      // [B, S, L]
    const int*   __restrict__ lens,        // [B]
    const float* __restrict__ trans,       // [L, L], trans[i*L+j]=score(j->i)
    float*       __restrict__ out,         // [B]
    int B)
{
    const int wid = threadIdx.x >> 5;
    const int k   = threadIdx.x & 31;
    const int b   = blockIdx.x * 4 + wid;
    if (b >= B) return;                    // warp-uniform

    __shared__ __align__(16) ull e_sm[4][2][NS];
    ull (*e_s)[NS] = e_sm[wid];

    const bool hasLo = (k <= 22);
    const bool hasHi = (k <= 21);
    const int  labLo = hasLo ? 2 * k : 0;          // clamped for dump lanes
    const int  labHi = hasHi ? 2 * k + 1 : (hasLo ? 44 : 0); // lane22 hi -> 44 (safe addr)

    // packed expT rows: rowp[j] = (expT[labLo][j], expT[labHi][j]); pads = 0
    ull rowp[46];
#pragma unroll
    for (int j = 0; j < L; j++) {
        const float rl = hasLo ? __expf(trans[labLo * L + j]) : 0.f;
        const float rh = hasHi ? __expf(trans[labHi * L + j]) : 0.f;
        rowp[j] = pack2(rl, rh);
    }
    rowp[45] = 0ull;                       // pad source label

    const int len = lens[b];
    const float* lg = logits + (size_t)b * SMAX * L;

    // ---- t = 0 analytically: alpha0 = logit[0] + T[:, START] ----
    const float a0lo = lg[labLo] + trans[labLo * L + START_IDX];
    const float a0hi = lg[labHi] + trans[labHi * L + START_IDX];
    const float mu0 = __shfl_sync(FULLM, a0lo, 0);
    float M2 = mu0 * LOG2E;                // running scale (base-2)
    float eLo = ex2f((a0lo - mu0) * LOG2E);
    float eHi = hasHi ? ex2f((a0hi - mu0) * LOG2E) : 0.f;  // setup-time sel ok
    ((ulonglong2*)e_s[1])[k] = make_ulonglong2(pack2(eLo, eLo), pack2(eHi, eHi));
    float cn = 0.f;                        // scale increment for step 1

    // ---- prefetch logits (clamped addresses; never-consumed slots ok) ----
    float lgLoB[PF], lgHiB[PF];
#pragma unroll
    for (int u = 0; u < PF; u++) {
        const int tc = min(1 + u, len - 1);
        lgLoB[u] = lg[tc * L + labLo];
        lgHiB[u] = lg[tc * L + labHi];
    }

#define STEP(tt, uu) do {                                                     \
        const int p_ = (tt) & 1;                                              \
        __syncwarp();                                                         \
        const float c2_ = __shfl_sync(FULLM, cn, 0);                          \
        const float lgtLo_ = lgLoB[uu];                                       \
        const float lgtHi_ = lgHiB[uu];                                       \
        { const int tc_ = min((tt) + PF, len - 1);                            \
          lgLoB[uu] = lg[tc_ * L + labLo];                                    \
          lgHiB[uu] = lg[tc_ * L + labHi]; }                                  \
        const ulonglong2* e2_ = (const ulonglong2*)(e_s[p_]);                 \
        ull ac_[4] = {0, 0, 0, 0};                                            \
        _Pragma("unroll")                                                     \
        for (int h_ = 0; h_ < 23; h_++) {                                     \
            const ulonglong2 w_ = e2_[h_];                                    \
            fma2(ac_[(2 * h_)     & 3], rowp[2 * h_],     w_.x);              \
            fma2(ac_[(2 * h_ + 1) & 3], rowp[2 * h_ + 1], w_.y);              \
        }                                                                     \
        add2(ac_[0], ac_[2]); add2(ac_[1], ac_[3]); add2(ac_[0], ac_[1]);     \
        const float2 s2_ = unpack2(ac_[0]);                                   \
        const float xLo_ = fmaf(lgtLo_, LOG2E, -c2_);                         \
        const float xHi_ = fmaf(lgtHi_, LOG2E, -c2_);                         \
        eLo = s2_.x * ex2f(xLo_);                                             \
        eHi = s2_.y * ex2f(xHi_);                                             \
        ((ulonglong2*)e_s[p_ ^ 1])[k] =                                       \
            make_ulonglong2(pack2(eLo, eLo), pack2(eHi, eHi));                \
        cn = lg2f(s2_.x) + xLo_;           /* off-path; lane 0's is used */   \
        M2 += c2_;                                                            \
    } while (0)

    // main loop: per-warp (len uniform across lanes), full PF-chunks + tail
    int t = 1;
    for (; t + PF <= len; t += PF) {
        STEP(t + 0, 0);
        STEP(t + 1, 1);
        STEP(t + 2, 2);
        STEP(t + 3, 3);
    }
    if (t < len) { STEP(t, 0); t++; }
    if (t < len) { STEP(t, 1); t++; }
    if (t < len) { STEP(t, 2); }
#undef STEP

    // ---- epilogue: out[b] = LSE_i( alpha_i + T[STOP, i] ) ----
    float vLo = -1e30f, vHi = -1e30f;
    if (hasLo) vLo = (M2 + lg2f(eLo)) * LN2 + trans[STOP_IDX * L + labLo];
    if (hasHi) vHi = (M2 + lg2f(eHi)) * LN2 + trans[STOP_IDX * L + labHi];
    float m = fmaxf(vLo, vHi);
#pragma unroll
    for (int off = 16; off; off >>= 1)
        m = fmaxf(m, __shfl_xor_sync(FULLM, m, off));
    float s = (hasLo ? ex2f((vLo - m) * LOG2E) : 0.f)
            + (hasHi ? ex2f((vHi - m) * LOG2E) : 0.f);
#pragma unroll
    for (int off = 16; off; off >>= 1)
        s += __shfl_xor_sync(FULLM, s, off);
    if (k == 0) out[b] = m + lg2f(s) * LN2;
}

extern "C" void kernel_launch(void* const* d_in, const int* in_sizes, int n_in,
                              void* d_out, int out_size) {
    const float* logits = (const float*)d_in[0];   // [1024, 512, 45] f32
    const int*   lens   = (const int*)d_in[1];     // [1024] i32
    const float* trans  = (const float*)d_in[2];   // [45, 45] f32
    float* out = (float*)d_out;                    // [1024] f32

    const int B = in_sizes[1];                     // 1024
    crf_fwd_kernel<<<(B + 3) / 4, 128>>>(logits, lens, trans, out, B);
}

// round 13
// speedup vs baseline: 1.2941x; 1.2941x over previous
#include <cuda_runtime.h>
#include <cuda_bf16.h>

#define L 45
#define LP 48              // padded label count
#define SMAX 512
#define START_IDX 43
#define STOP_IDX 44
#define PF 4               // logit prefetch distance
#define LOG2E 1.4426950408889634f
#define LN2   0.6931471805599453f

__device__ __forceinline__ float ex2f(float x) {
    float r; asm("ex2.approx.ftz.f32 %0, %1;" : "=f"(r) : "f"(x)); return r;
}
__device__ __forceinline__ float lg2f(float x) {
    float r; asm("lg2.approx.ftz.f32 %0, %1;" : "=f"(r) : "f"(x)); return r;
}
__device__ __forceinline__ void fma2(unsigned long long& d,
                                     unsigned long long a, unsigned long long b) {
    asm("fma.rn.f32x2 %0, %1, %2, %0;" : "+l"(d) : "l"(a), "l"(b));
}
__device__ __forceinline__ void add2(unsigned long long& d, unsigned long long a) {
    asm("add.rn.f32x2 %0, %0, %1;" : "+l"(d) : "l"(a));
}
__device__ __forceinline__ unsigned long long pack2(float lo, float hi) {
    unsigned long long v;
    asm("mov.b64 %0, {%1, %2};" : "=l"(v) : "f"(lo), "f"(hi)); return v;
}
__device__ __forceinline__ float2 unpack2(unsigned long long v) {
    float2 f; asm("mov.b64 {%0, %1}, %2;" : "=f"(f.x), "=f"(f.y) : "l"(v)); return f;
}

// EXACT R3-best step body (111.3us kernel), re-housed for SMSP balance:
// 128-thread block = TWO independent batches with WARP-SWIZZLED pairing:
//   pair 0 (batch 2*bid)   = warps {0, 3}  -> SMSPs 0 and 3
//   pair 1 (batch 2*bid+1) = warps {1, 2}  -> SMSPs 1 and 2
// so all four SMSPs carry R3-grade (~110 issue/step) warps instead of SMSP0/1
// carrying everything. Each pair syncs with its own named barrier (id 1 / 2,
// count 64) -- only 2 named bars per block-step (R5's failure used 4), each
// coupling exactly 2 warps (R3-proven skew).
// Per pair, i in [0,64): i<45 e-producers (expT row in regs, packed f32x2
// j-dot), i==45 dedicated scale-increment producer (copy of row 0; its lg2
// runs in parallel with everyone's ex2).
// Recurrence (base-2, scaled-linear): s_i = sum_j expT[i,j]*e[j];
//   e'_i = s_i * 2^(lgt2_i - c2);  M2 += c2;  c2' = lg2(s_0)+lgt2_0-c2 (stale).
__global__ __launch_bounds__(128) void crf_fwd_kernel(
    const float* __restrict__ logits,      // [B, S, L]
    const int*   __restrict__ lens,        // [B]
    const float* __restrict__ trans,       // [L, L], trans[i*L+j]=score(j->i)
    float*       __restrict__ out)         // [B]
{
    const int wid  = threadIdx.x >> 5;
    const int lane = threadIdx.x & 31;
    const int pair = (wid == 0 || wid == 3) ? 0 : 1;   // warp-swizzled pairing
    const int half = (wid >> 1);                        // warps 2,3 -> upper half
    const int i    = half * 32 + lane;                  // label index in pair
    const int b    = blockIdx.x * 2 + pair;
    const int bar  = pair + 1;                          // named barrier id

    __shared__ __align__(16) float e_sm[2][2][LP];
    __shared__ float c_sm[2][2];
    __shared__ float m_sm[2];
    __shared__ float red_sm[2][64];

    float (*e_s)[LP] = e_sm[pair];
    float* c_s = c_sm[pair];
    float* red = red_sm[pair];

    const bool is_e = (i < L);
    const bool is_c = (i == L);            // thread 45 of the pair
    const bool ld   = is_e | is_c;
    const int  lab  = is_e ? i : 0;

    if (i < LP) { e_s[0][i] = 0.f; e_s[1][i] = 0.f; }
    if (i == 0) { c_s[0] = 0.f; c_s[1] = 0.f; }

    // packed expT row in registers (j-pairs)
    unsigned long long rowp[LP / 2];
#pragma unroll
    for (int m = 0; m < LP / 2; m++) rowp[m] = 0ull;
    if (ld) {
#pragma unroll
        for (int m = 0; m < LP / 2; m++) {
            const float x0 = __expf(trans[lab * L + 2 * m]);
            const float x1 = (2 * m + 1 < L) ? __expf(trans[lab * L + 2 * m + 1]) : 0.f;
            rowp[m] = pack2(x0, x1);
        }
    }

    const int len = lens[b];
    const float* lg = logits + (size_t)b * SMAX * L;

    // ---- t = 0 analytically: alpha0 = logit[0] + T[:, START] ----
    float a0v = 0.f;
    if (is_e) a0v = lg[i] + trans[i * L + START_IDX];
    if (i == 0) m_sm[pair] = a0v;
    asm volatile("bar.sync %0, 64;" :: "r"(bar) : "memory");
    const float mu0 = m_sm[pair];
    float M2 = mu0 * LOG2E;                // running scale (base-2)
    float e_loc = ex2f((a0v - mu0) * LOG2E);
    if (is_e) e_s[1][i] = e_loc;

    // ---- prefetch logits (pre-scaled by log2e) ----
    float lgbuf[PF];
#pragma unroll
    for (int u = 0; u < PF; u++) {
        const int t = 1 + u;
        lgbuf[u] = (ld && t < len) ? lg[t * L + lab] * LOG2E : 0.f;
    }

#define STEP(tt, uu) do {                                                     \
        const int p_ = (tt) & 1;                                              \
        asm volatile("bar.sync %0, 64;" :: "r"(bar) : "memory");              \
        const float lgt2_ = lgbuf[uu];                                        \
        { const int tn_ = (tt) + PF;                                          \
          lgbuf[uu] = (ld && tn_ < len) ? lg[tn_ * L + lab] * LOG2E : 0.f; }  \
        const float c2_ = c_s[p_ ^ 1];                                        \
        const ulonglong2* e2_ = (const ulonglong2*)(e_s[p_]);                 \
        unsigned long long ac_[8] = {0,0,0,0,0,0,0,0};                        \
        _Pragma("unroll")                                                     \
        for (int h_ = 0; h_ < LP / 4; h_++) {                                 \
            const ulonglong2 w_ = e2_[h_];                                    \
            fma2(ac_[(2 * h_)     & 7], rowp[2 * h_],     w_.x);              \
            fma2(ac_[(2 * h_ + 1) & 7], rowp[2 * h_ + 1], w_.y);              \
        }                                                                     \
        add2(ac_[0], ac_[4]); add2(ac_[1], ac_[5]);                           \
        add2(ac_[2], ac_[6]); add2(ac_[3], ac_[7]);                           \
        add2(ac_[0], ac_[2]); add2(ac_[1], ac_[3]);                           \
        add2(ac_[0], ac_[1]);                                                 \
        const float2 f_ = unpack2(ac_[0]);                                    \
        const float s_ = f_.x + f_.y;                                         \
        if (is_e) {                                                           \
            const float en_ = s_ * ex2f(lgt2_ - c2_);                         \
            e_s[p_ ^ 1][i] = en_; e_loc = en_;                                \
        }                                                                     \
        if (is_c) c_s[p_] = lg2f(s_) + lgt2_ - c2_;                           \
        M2 += c2_;                                                            \
    } while (0)

    // main loop: full PF-chunks, branch-free bodies (prefetch is predicated)
    int t = 1;
    for (; t + PF <= len; t += PF) {
        STEP(t + 0, 0);
        STEP(t + 1, 1);
        STEP(t + 2, 2);
        STEP(t + 3, 3);
    }
    // tail (<= 3 steps), constant lgbuf indices
    if (t < len) { STEP(t, 0); t++; }
    if (t < len) { STEP(t, 1); t++; }
    if (t < len) { STEP(t, 2); }
#undef STEP

    // ---- epilogue: out[b] = LSE_i( alpha_i + T[STOP, i] ) ----
    red[i] = is_e ? ((M2 + lg2f(e_loc)) * LN2 + trans[STOP_IDX * L + i]) : -1e30f;
    asm volatile("bar.sync %0, 64;" :: "r"(bar) : "memory");
    if (i == 0) {
        float m = red[0];
#pragma unroll
        for (int j = 1; j < L; j++) m = fmaxf(m, red[j]);
        float s = 0.f;
#pragma unroll
        for (int j = 0; j < L; j++) s += __expf(red[j] - m);
        out[b] = m + __logf(s);
    }
}

extern "C" void kernel_launch(void* const* d_in, const int* in_sizes, int n_in,
                              void* d_out, int out_size) {
    const float* logits = (const float*)d_in[0];   // [1024, 512, 45] f32
    const int*   lens   = (const int*)d_in[1];     // [1024] i32
    const float* trans  = (const float*)d_in[2];   // [45, 45] f32
    float* out = (float*)d_out;                    // [1024] f32

    const int B = in_sizes[1];                     // 1024
    crf_fwd_kernel<<<B / 2, 128>>>(logits, lens, trans, out);
}

// round 14
// speedup vs baseline: 1.6728x; 1.2926x over previous
#include <cuda_runtime.h>
#include <cuda_bf16.h>

#define L 45
#define LP 48              // padded label count
#define SMAX 512
#define START_IDX 43
#define STOP_IDX 44
#define PF 4               // logit prefetch distance
#define NB 1024            // batch size (fixed for this problem)
#define LOG2E 1.4426950408889634f
#define LN2   0.6931471805599453f

__device__ __forceinline__ float ex2f(float x) {
    float r; asm("ex2.approx.ftz.f32 %0, %1;" : "=f"(r) : "f"(x)); return r;
}
__device__ __forceinline__ float lg2f(float x) {
    float r; asm("lg2.approx.ftz.f32 %0, %1;" : "=f"(r) : "f"(x)); return r;
}
__device__ __forceinline__ void fma2(unsigned long long& d,
                                     unsigned long long a, unsigned long long b) {
    asm("fma.rn.f32x2 %0, %1, %2, %0;" : "+l"(d) : "l"(a), "l"(b));
}
__device__ __forceinline__ void add2(unsigned long long& d, unsigned long long a) {
    asm("add.rn.f32x2 %0, %0, %1;" : "+l"(d) : "l"(a));
}
__device__ __forceinline__ unsigned long long pack2(float lo, float hi) {
    unsigned long long v;
    asm("mov.b64 %0, {%1, %2};" : "=l"(v) : "f"(lo), "f"(hi)); return v;
}
__device__ __forceinline__ float2 unpack2(unsigned long long v) {
    float2 f; asm("mov.b64 {%0, %1}, %2;" : "=f"(f.x), "=f"(f.y) : "l"(v)); return f;
}

// permutation of batch indices, sorted by descending length
__device__ int d_perm[NB];

// ---- pre-pass: bitonic sort of (len desc, idx) keys, one 1024-thread block ----
__global__ void sort_lens_kernel(const int* __restrict__ lens, int B) {
    __shared__ unsigned sk[NB];
    const int t = threadIdx.x;
    const int len = (t < B) ? lens[t] : 0;
    // ascending sort of (SMAX-len, idx)  ==  descending by len, idx tiebreak
    sk[t] = ((unsigned)(SMAX - len) << 12) | (unsigned)t;
    __syncthreads();
    for (int k = 2; k <= NB; k <<= 1) {
        for (int j = k >> 1; j > 0; j >>= 1) {
            const int ixj = t ^ j;
            if (ixj > t) {
                const unsigned a = sk[t], c = sk[ixj];
                const bool up = ((t & k) == 0);
                if (up ? (a > c) : (a < c)) { sk[t] = c; sk[ixj] = a; }
            }
            __syncthreads();
        }
    }
    d_perm[t] = (int)(sk[t] & 0xFFFu);
}

// ---- main kernel: EXACT R3-best step body (111.3us), bin-packed schedule ----
// 512 blocks x 64 threads; block j runs batch perm[j] (long) then batch
// perm[1023-j] (short) SEQUENTIALLY. Uniform lens => every block totals ~513
// steps: perfect load balance, and only ~3.46 blocks/SM instead of 6.9 =>
// half the warp contention on SMSP 0/1 for the whole run, no tail.
// Per batch, thread i: i<45 e-producers (expT row in regs, packed f32x2
// j-dot), i==45 dedicated scale-increment producer (copy of row 0; its lg2
// runs in parallel with everyone's ex2). Sync = one plain BAR0 per step.
// Recurrence (base-2, scaled-linear): s_i = sum_j expT[i,j]*e[j];
//   e'_i = s_i * 2^(lgt2_i - c2);  M2 += c2;  c2' = lg2(s_0)+lgt2_0-c2 (stale).
__global__ __launch_bounds__(64) void crf_fwd_kernel(
    const float* __restrict__ logits,      // [B, S, L]
    const int*   __restrict__ lens,        // [B]
    const float* __restrict__ trans,       // [L, L], trans[i*L+j]=score(j->i)
    float*       __restrict__ out)         // [B]
{
    const int i = threadIdx.x;

    __shared__ __align__(16) float e_s[2][LP];
    __shared__ float c_s[2];
    __shared__ float m_s;
    __shared__ float red[64];

    const bool is_e = (i < L);
    const bool is_c = (i == L);            // thread 45
    const bool ld   = is_e | is_c;
    const int  lab  = is_e ? i : 0;

    // packed expT row in registers (shared by both batches -- same trans)
    unsigned long long rowp[LP / 2];
#pragma unroll
    for (int m = 0; m < LP / 2; m++) rowp[m] = 0ull;
    if (ld) {
#pragma unroll
        for (int m = 0; m < LP / 2; m++) {
            const float x0 = __expf(trans[lab * L + 2 * m]);
            const float x1 = (2 * m + 1 < L) ? __expf(trans[lab * L + 2 * m + 1]) : 0.f;
            rowp[m] = pack2(x0, x1);
        }
    }

    for (int q = 0; q < 2; q++) {
        const int b = d_perm[q == 0 ? blockIdx.x : (NB - 1 - blockIdx.x)];

        if (i < LP) { e_s[0][i] = 0.f; e_s[1][i] = 0.f; }
        if (i == 0) { c_s[0] = 0.f; c_s[1] = 0.f; }

        const int len = lens[b];
        const float* lg = logits + (size_t)b * SMAX * L;

        // ---- t = 0 analytically: alpha0 = logit[0] + T[:, START] ----
        float a0v = 0.f;
        if (is_e) a0v = lg[i] + trans[i * L + START_IDX];
        if (i == 0) m_s = a0v;
        __syncthreads();
        const float mu0 = m_s;
        float M2 = mu0 * LOG2E;            // running scale (base-2)
        float e_loc = ex2f((a0v - mu0) * LOG2E);
        if (is_e) e_s[1][i] = e_loc;

        // ---- prefetch logits (pre-scaled by log2e) ----
        float lgbuf[PF];
#pragma unroll
        for (int u = 0; u < PF; u++) {
            const int t = 1 + u;
            lgbuf[u] = (ld && t < len) ? lg[t * L + lab] * LOG2E : 0.f;
        }

#define STEP(tt, uu) do {                                                     \
        const int p_ = (tt) & 1;                                              \
        __syncthreads();                                                      \
        const float lgt2_ = lgbuf[uu];                                        \
        { const int tn_ = (tt) + PF;                                          \
          lgbuf[uu] = (ld && tn_ < len) ? lg[tn_ * L + lab] * LOG2E : 0.f; }  \
        const float c2_ = c_s[p_ ^ 1];                                        \
        const ulonglong2* e2_ = (const ulonglong2*)(e_s[p_]);                 \
        unsigned long long ac_[8] = {0,0,0,0,0,0,0,0};                        \
        _Pragma("unroll")                                                     \
        for (int h_ = 0; h_ < LP / 4; h_++) {                                 \
            const ulonglong2 w_ = e2_[h_];                                    \
            fma2(ac_[(2 * h_)     & 7], rowp[2 * h_],     w_.x);              \
            fma2(ac_[(2 * h_ + 1) & 7], rowp[2 * h_ + 1], w_.y);              \
        }                                                                     \
        add2(ac_[0], ac_[4]); add2(ac_[1], ac_[5]);                           \
        add2(ac_[2], ac_[6]); add2(ac_[3], ac_[7]);                           \
        add2(ac_[0], ac_[2]); add2(ac_[1], ac_[3]);                           \
        add2(ac_[0], ac_[1]);                                                 \
        const float2 f_ = unpack2(ac_[0]);                                    \
        const float s_ = f_.x + f_.y;                                         \
        if (is_e) {                                                           \
            const float en_ = s_ * ex2f(lgt2_ - c2_);                         \
            e_s[p_ ^ 1][i] = en_; e_loc = en_;                                \
        }                                                                     \
        if (is_c) c_s[p_] = lg2f(s_) + lgt2_ - c2_;                           \
        M2 += c2_;                                                            \
    } while (0)

        // main loop: full PF-chunks, branch-free bodies
        int t = 1;
        for (; t + PF <= len; t += PF) {
            STEP(t + 0, 0);
            STEP(t + 1, 1);
            STEP(t + 2, 2);
            STEP(t + 3, 3);
        }
        // tail (<= 3 steps), constant lgbuf indices
        if (t < len) { STEP(t, 0); t++; }
        if (t < len) { STEP(t, 1); t++; }
        if (t < len) { STEP(t, 2); }
#undef STEP

        // ---- epilogue: out[b] = LSE_i( alpha_i + T[STOP, i] ) ----
        red[i] = is_e ? ((M2 + lg2f(e_loc)) * LN2 + trans[STOP_IDX * L + i]) : -1e30f;
        __syncthreads();
        if (i == 0) {
            float m = red[0];
#pragma unroll
            for (int j = 1; j < L; j++) m = fmaxf(m, red[j]);
            float s = 0.f;
#pragma unroll
            for (int j = 0; j < L; j++) s += __expf(red[j] - m);
            out[b] = m + __logf(s);
        }
        __syncthreads();   // protect smem re-init of next batch
    }
}

extern "C" void kernel_launch(void* const* d_in, const int* in_sizes, int n_in,
                              void* d_out, int out_size) {
    const float* logits = (const float*)d_in[0];   // [1024, 512, 45] f32
    const int*   lens   = (const int*)d_in[1];     // [1024] i32
    const float* trans  = (const float*)d_in[2];   // [45, 45] f32
    float* out = (float*)d_out;                    // [1024] f32

    const int B = in_sizes[1];                     // 1024
    sort_lens_kernel<<<1, NB>>>(lens, B);
    crf_fwd_kernel<<<B / 2, 64>>>(logits, lens, trans, out);
}